// round 2
// baseline (speedup 1.0000x reference)
#include <cuda_runtime.h>
#include <math.h>

#define TT 1024
#define DD 256
#define HH 256
#define NSCAN 1025

// ---------------- scratch (static __device__ globals; no allocation) ----------------
__device__ float g_K[TT*HH];
__device__ float g_Q[TT*HH];
__device__ float g_V[TT*HH];
__device__ float g_SKIP[TT*HH];
__device__ float g_S[TT*TT];
__device__ float g_OUT[TT*HH];
__device__ float g_H1[TT*HH];
__device__ float g_H2[TT*HH];
__device__ float g_H3[TT*HH];
__device__ float g_sumk[TT];
__device__ float g_sumq[TT];
__device__ float g_denom[TT];
__device__ unsigned g_E[2048*33];          // element masks, all levels
__device__ unsigned g_P[2][NSCAN*33];      // prefix masks ping-pong
__device__ unsigned g_AM[TT*32];           // final attention mask bits [t][u]

__device__ __forceinline__ float eluf(float x){ return x > 0.f ? x : expm1f(x); }
__device__ __forceinline__ float mishf(float x){
    float sp = (x > 20.f) ? x : log1pf(expf(x));
    return x * tanhf(sp);
}

// ---------------- mask kernel: replicate jax.lax.associative_scan tree exactly ----------------
// Scan over NSCAN=1025 elements (element 0 = zero state). combine(a,b):
//   mask = (mask_a if start[last(b)]) | (mask_b if done[last(b)]); gates(result)=gates(last(b)).
// Down-sweep builds reduced-element masks per level; up-sweep builds prefixes:
//   P_l[0]=E_l[0]; P_l[2k+1]=P_{l+1}[k]; P_l[2k]=combine(P_l[2k-1], E_l[2k]).
__global__ __launch_bounds__(1024) void mask_kernel(const int* __restrict__ start,
                                                    const int* __restrict__ done)
{
    const int Ns[11]  = {1025,512,256,128,64,32,16,8,4,2,1};
    const int off[11] = {0,1025,1537,1793,1921,1985,2017,2033,2041,2045,2047};
    int tid = threadIdx.x, nth = blockDim.x;

    // level-0 element masks: E0[i] = {i}
    for (int idx = tid; idx < 1025*33; idx += nth) {
        int e = idx / 33, w = idx - e*33;
        g_E[e*33 + w] = (w == (e >> 5)) ? (1u << (e & 31)) : 0u;
    }
    __syncthreads();

    // down-sweep
    for (int l = 0; l < 10; l++) {
        int n2 = Ns[l+1];
        for (int idx = tid; idx < n2*33; idx += nth) {
            int m = idx / 33, w = idx - m*33;
            int lastb = ((2*m + 2) << l) - 1;   // last original index of right child
            unsigned stm = start[lastb] ? 0xFFFFFFFFu : 0u;
            unsigned dnm = done[lastb]  ? 0xFFFFFFFFu : 0u;
            g_E[(off[l+1] + m)*33 + w] =
                (g_E[(off[l] + 2*m)*33 + w] & stm) | (g_E[(off[l] + 2*m + 1)*33 + w] & dnm);
        }
        __syncthreads();
    }

    // up-sweep
    int cur = 0;
    for (int w = tid; w < 33; w += nth) g_P[0][w] = g_E[off[10]*33 + w];
    __syncthreads();
    for (int l = 9; l >= 0; l--) {
        int nxt = cur ^ 1;
        int nl = Ns[l];
        for (int idx = tid; idx < nl*33; idx += nth) {
            int p = idx / 33, w = idx - p*33;
            unsigned v;
            if (p == 0) {
                v = g_E[off[l]*33 + w];
            } else if (p & 1) {
                v = g_P[cur][(p >> 1)*33 + w];
            } else {
                int lastp = ((p + 1) << l) - 1;
                unsigned stm = start[lastp] ? 0xFFFFFFFFu : 0u;
                unsigned dnm = done[lastp]  ? 0xFFFFFFFFu : 0u;
                v = (g_P[cur][((p >> 1) - 1)*33 + w] & stm) | (g_E[(off[l] + p)*33 + w] & dnm);
            }
            g_P[nxt][p*33 + w] = v;
        }
        __syncthreads();
        cur = nxt;
    }

    // attention mask: output row t uses prefix at scan position t+1; kv u -> scan element u+1
    for (int idx = tid; idx < 1024*32; idx += nth) {
        int t = idx >> 5, w = idx & 31;
        unsigned lo = g_P[cur][(t + 1)*33 + w];
        unsigned hi = g_P[cur][(t + 1)*33 + w + 1];
        g_AM[t*32 + w] = (lo >> 1) | (hi << 31);
    }
}

// ---------------- GEMM: C[M,N] = act(A[M,K] @ B[N,K]^T + bias) ----------------
// ACT: 0=none, 1=elu, 2=mish, 3=mask-score (zero where mask bit clear, no bias)
template<int ACT>
__global__ __launch_bounds__(256) void gemm_abt(const float* __restrict__ A,
                                                const float* __restrict__ B,
                                                const float* __restrict__ bias,
                                                float* __restrict__ C,
                                                int M, int N, int K)
{
    __shared__ float As[32][64];   // [kk][row]
    __shared__ float Bs[32][64];   // [kk][col]
    int tid = threadIdx.x;
    int tx = tid & 15, ty = tid >> 4;
    int arow0 = blockIdx.y * 64, brow0 = blockIdx.x * 64;
    float acc[4][4] = {};
    int lr = tid >> 2, lc = (tid & 3) << 3;
    const float* Ap = A + (size_t)(arow0 + lr) * K + lc;
    const float* Bp = B + (size_t)(brow0 + lr) * K + lc;

    for (int k0 = 0; k0 < K; k0 += 32) {
        float4 a0 = *(const float4*)(Ap + k0);
        float4 a1 = *(const float4*)(Ap + k0 + 4);
        float4 b0 = *(const float4*)(Bp + k0);
        float4 b1 = *(const float4*)(Bp + k0 + 4);
        As[lc+0][lr]=a0.x; As[lc+1][lr]=a0.y; As[lc+2][lr]=a0.z; As[lc+3][lr]=a0.w;
        As[lc+4][lr]=a1.x; As[lc+5][lr]=a1.y; As[lc+6][lr]=a1.z; As[lc+7][lr]=a1.w;
        Bs[lc+0][lr]=b0.x; Bs[lc+1][lr]=b0.y; Bs[lc+2][lr]=b0.z; Bs[lc+3][lr]=b0.w;
        Bs[lc+4][lr]=b1.x; Bs[lc+5][lr]=b1.y; Bs[lc+6][lr]=b1.z; Bs[lc+7][lr]=b1.w;
        __syncthreads();
        #pragma unroll
        for (int kk = 0; kk < 32; kk++) {
            float4 av = *(const float4*)&As[kk][ty*4];
            float4 bv = *(const float4*)&Bs[kk][tx*4];
            float a[4] = {av.x, av.y, av.z, av.w};
            float b[4] = {bv.x, bv.y, bv.z, bv.w};
            #pragma unroll
            for (int r = 0; r < 4; r++)
                #pragma unroll
                for (int c = 0; c < 4; c++)
                    acc[r][c] += a[r] * b[c];
        }
        __syncthreads();
    }

    #pragma unroll
    for (int r = 0; r < 4; r++) {
        int row = arow0 + ty*4 + r;
        #pragma unroll
        for (int c = 0; c < 4; c++) {
            int col = brow0 + tx*4 + c;
            float v = acc[r][c];
            if (ACT != 3 && bias) v += bias[col];
            if (ACT == 1) v = eluf(v);
            else if (ACT == 2) v = mishf(v);
            else if (ACT == 3) {
                unsigned mw = g_AM[row*32 + (col >> 5)];
                v = ((mw >> (col & 31)) & 1u) ? v : 0.f;
            }
            C[(size_t)row * N + col] = v;
        }
    }
}

// ---------------- GEMM: C[M,N] = (A[M,K] @ B[K,N]) / denom[row] ----------------
__global__ __launch_bounds__(256) void gemm_ab_div(const float* __restrict__ A,
                                                   const float* __restrict__ B,
                                                   float* __restrict__ C,
                                                   int M, int N, int K)
{
    __shared__ float As[32][64];   // [kk][row]
    __shared__ float Bs[32][64];   // [kk][col]
    int tid = threadIdx.x;
    int tx = tid & 15, ty = tid >> 4;
    int arow0 = blockIdx.y * 64, bcol0 = blockIdx.x * 64;
    float acc[4][4] = {};
    int lr = tid >> 2, lc = (tid & 3) << 3;          // A loader
    int br = tid >> 3, bc = (tid & 7) << 3;          // B loader

    for (int k0 = 0; k0 < K; k0 += 32) {
        float4 a0 = *(const float4*)&A[(size_t)(arow0 + lr) * K + k0 + lc];
        float4 a1 = *(const float4*)&A[(size_t)(arow0 + lr) * K + k0 + lc + 4];
        float4 b0 = *(const float4*)&B[(size_t)(k0 + br) * N + bcol0 + bc];
        float4 b1 = *(const float4*)&B[(size_t)(k0 + br) * N + bcol0 + bc + 4];
        As[lc+0][lr]=a0.x; As[lc+1][lr]=a0.y; As[lc+2][lr]=a0.z; As[lc+3][lr]=a0.w;
        As[lc+4][lr]=a1.x; As[lc+5][lr]=a1.y; As[lc+6][lr]=a1.z; As[lc+7][lr]=a1.w;
        *(float4*)&Bs[br][bc]     = b0;
        *(float4*)&Bs[br][bc + 4] = b1;
        __syncthreads();
        #pragma unroll
        for (int kk = 0; kk < 32; kk++) {
            float4 av = *(const float4*)&As[kk][ty*4];
            float4 bv = *(const float4*)&Bs[kk][tx*4];
            float a[4] = {av.x, av.y, av.z, av.w};
            float b[4] = {bv.x, bv.y, bv.z, bv.w};
            #pragma unroll
            for (int r = 0; r < 4; r++)
                #pragma unroll
                for (int c = 0; c < 4; c++)
                    acc[r][c] += a[r] * b[c];
        }
        __syncthreads();
    }

    #pragma unroll
    for (int r = 0; r < 4; r++) {
        int row = arow0 + ty*4 + r;
        float inv = 1.0f / g_denom[row];
        #pragma unroll
        for (int c = 0; c < 4; c++) {
            int col = bcol0 + tx*4 + c;
            C[(size_t)row * N + col] = acc[r][c] * inv;
        }
    }
}

// ---------------- row sums of elu'd K and Q ----------------
__global__ __launch_bounds__(256) void rowsums_kernel()
{
    __shared__ float sk[256], sq[256];
    int t = blockIdx.x, j = threadIdx.x;
    sk[j] = g_K[t*HH + j];
    sq[j] = g_Q[t*HH + j];
    __syncthreads();
    for (int s = 128; s > 0; s >>= 1) {
        if (j < s) { sk[j] += sk[j+s]; sq[j] += sq[j+s]; }
        __syncthreads();
    }
    if (j == 0) { g_sumk[t] = sk[0]; g_sumq[t] = sq[0]; }
}

// ---------------- denom[t] = max(sumq[t] * sum_u mask[t][u]*sumk[u], 1e-5) ----------------
__global__ __launch_bounds__(256) void denom_kernel()
{
    __shared__ float red[256];
    int t = blockIdx.x, j = threadIdx.x;
    float s = 0.f;
    for (int u = j; u < TT; u += 256) {
        unsigned mw = g_AM[t*32 + (u >> 5)];
        if ((mw >> (u & 31)) & 1u) s += g_sumk[u];
    }
    red[j] = s;
    __syncthreads();
    for (int st = 128; st > 0; st >>= 1) {
        if (j < st) red[j] += red[j+st];
        __syncthreads();
    }
    if (j == 0) g_denom[t] = fmaxf(red[0] * g_sumq[t], 1e-5f);
}

// ---------------- final: layernorm(H3 + SKIP) ----------------
__global__ __launch_bounds__(256) void ln_kernel(const float* __restrict__ lnw,
                                                 const float* __restrict__ lnb,
                                                 float* __restrict__ out)
{
    __shared__ float red[256];
    int t = blockIdx.x, j = threadIdx.x;
    float h = g_H3[t*HH + j] + g_SKIP[t*HH + j];
    red[j] = h;
    __syncthreads();
    for (int s = 128; s > 0; s >>= 1) { if (j < s) red[j] += red[j+s]; __syncthreads(); }
    float mu = red[0] * (1.0f / HH);
    __syncthreads();
    float d = h - mu;
    red[j] = d * d;
    __syncthreads();
    for (int s = 128; s > 0; s >>= 1) { if (j < s) red[j] += red[j+s]; __syncthreads(); }
    float var = red[0] * (1.0f / HH);
    out[t*HH + j] = d * rsqrtf(var + 1e-5f) * lnw[j] + lnb[j];
}

// ---------------- launch ----------------
extern "C" void kernel_launch(void* const* d_in, const int* in_sizes, int n_in,
                              void* d_out, int out_size)
{
    const float* x     = (const float*)d_in[0];
    const int*   start = (const int*)  d_in[3];
    const int*   done  = (const int*)  d_in[4];
    const float* Wk    = (const float*)d_in[5];
    const float* Wq    = (const float*)d_in[6];
    const float* Wv    = (const float*)d_in[7];
    const float* Wskip = (const float*)d_in[8];
    const float* bskip = (const float*)d_in[9];
    const float* W1    = (const float*)d_in[10];
    const float* b1    = (const float*)d_in[11];
    const float* W2    = (const float*)d_in[12];
    const float* b2    = (const float*)d_in[13];
    const float* W3    = (const float*)d_in[14];
    const float* b3    = (const float*)d_in[15];
    const float* lnw   = (const float*)d_in[16];
    const float* lnb   = (const float*)d_in[17];
    float* out = (float*)d_out;

    float *pK, *pQ, *pV, *pSKIP, *pS, *pOUT, *pH1, *pH2, *pH3;
    cudaGetSymbolAddress((void**)&pK,    g_K);
    cudaGetSymbolAddress((void**)&pQ,    g_Q);
    cudaGetSymbolAddress((void**)&pV,    g_V);
    cudaGetSymbolAddress((void**)&pSKIP, g_SKIP);
    cudaGetSymbolAddress((void**)&pS,    g_S);
    cudaGetSymbolAddress((void**)&pOUT,  g_OUT);
    cudaGetSymbolAddress((void**)&pH1,   g_H1);
    cudaGetSymbolAddress((void**)&pH2,   g_H2);
    cudaGetSymbolAddress((void**)&pH3,   g_H3);

    dim3 blk(256);
    dim3 grid_proj(HH/64, TT/64);    // (4,16)
    dim3 grid_score(TT/64, TT/64);   // (16,16)

    mask_kernel<<<1, 1024>>>(start, done);
    gemm_abt<1><<<grid_proj, blk>>>(x, Wk, nullptr, pK, TT, HH, DD);
    gemm_abt<1><<<grid_proj, blk>>>(x, Wq, nullptr, pQ, TT, HH, DD);
    gemm_abt<0><<<grid_proj, blk>>>(x, Wv, nullptr, pV, TT, HH, DD);
    gemm_abt<0><<<grid_proj, blk>>>(x, Wskip, bskip, pSKIP, TT, HH, DD);
    rowsums_kernel<<<TT, 256>>>();
    gemm_abt<3><<<grid_score, blk>>>(pQ, pK, nullptr, pS, TT, TT, HH);
    denom_kernel<<<TT, 256>>>();
    gemm_ab_div<<<grid_proj, blk>>>(pS, pV, pOUT, TT, HH, TT);
    gemm_abt<2><<<grid_proj, blk>>>(pOUT, W1, b1, pH1, TT, HH, HH);
    gemm_abt<2><<<grid_proj, blk>>>(pH1, W2, b2, pH2, TT, HH, HH);
    gemm_abt<0><<<grid_proj, blk>>>(pH2, W3, b3, pH3, TT, HH, HH);
    ln_kernel<<<TT, 256>>>(lnw, lnb, out);
}

// round 3
// speedup vs baseline: 1.5964x; 1.5964x over previous
#include <cuda_runtime.h>
#include <math.h>

#define TT 1024
#define DD 256
#define HH 256
#define NSCAN 1025

// ---------------- scratch (static __device__ globals; no allocation) ----------------
__device__ float g_K[TT*HH];
__device__ float g_Q[TT*HH];
__device__ float g_V[TT*HH];
__device__ float g_SKIP[TT*HH];
__device__ float g_S[TT*TT];
__device__ float g_SVP[4*TT*HH];       // split-K partials for S@V
__device__ float g_OUT[TT*HH];
__device__ float g_H1[TT*HH];
__device__ float g_H2[TT*HH];
__device__ float g_H3[TT*HH];
__device__ float g_sumk[TT];
__device__ float g_sumq[TT];
__device__ float g_denom[TT];
__device__ unsigned g_E[2048*33];
__device__ unsigned g_P[2][NSCAN*33];
__device__ unsigned g_AM[TT*32];

struct SegPtrs { const float* W[4]; float* out[4]; const float* b; };

union U64 { unsigned long long u; float2 f; };
__device__ __forceinline__ void ffma2(U64& d, const U64& a, const U64& b){
    asm("fma.rn.f32x2 %0, %1, %2, %0;" : "+l"(d.u) : "l"(a.u), "l"(b.u));
}

__device__ __forceinline__ float eluf(float x){ return x > 0.f ? x : expm1f(x); }
__device__ __forceinline__ float mishf(float x){
    float sp = (x > 20.f) ? x : log1pf(expf(x));
    return x * tanhf(sp);
}

// ---------------- mask kernel: replicate jax.lax.associative_scan tree exactly ----------------
__global__ __launch_bounds__(1024) void mask_kernel(const int* __restrict__ start,
                                                    const int* __restrict__ done)
{
    const int Ns[11]  = {1025,512,256,128,64,32,16,8,4,2,1};
    const int off[11] = {0,1025,1537,1793,1921,1985,2017,2033,2041,2045,2047};
    int tid = threadIdx.x, nth = blockDim.x;

    for (int idx = tid; idx < 1025*33; idx += nth) {
        int e = idx / 33, w = idx - e*33;
        g_E[e*33 + w] = (w == (e >> 5)) ? (1u << (e & 31)) : 0u;
    }
    __syncthreads();

    for (int l = 0; l < 10; l++) {
        int n2 = Ns[l+1];
        for (int idx = tid; idx < n2*33; idx += nth) {
            int m = idx / 33, w = idx - m*33;
            int lastb = ((2*m + 2) << l) - 1;
            unsigned stm = start[lastb] ? 0xFFFFFFFFu : 0u;
            unsigned dnm = done[lastb]  ? 0xFFFFFFFFu : 0u;
            g_E[(off[l+1] + m)*33 + w] =
                (g_E[(off[l] + 2*m)*33 + w] & stm) | (g_E[(off[l] + 2*m + 1)*33 + w] & dnm);
        }
        __syncthreads();
    }

    int cur = 0;
    for (int w = tid; w < 33; w += nth) g_P[0][w] = g_E[off[10]*33 + w];
    __syncthreads();
    for (int l = 9; l >= 0; l--) {
        int nxt = cur ^ 1;
        int nl = Ns[l];
        for (int idx = tid; idx < nl*33; idx += nth) {
            int p = idx / 33, w = idx - p*33;
            unsigned v;
            if (p == 0) {
                v = g_E[off[l]*33 + w];
            } else if (p & 1) {
                v = g_P[cur][(p >> 1)*33 + w];
            } else {
                int lastp = ((p + 1) << l) - 1;
                unsigned stm = start[lastp] ? 0xFFFFFFFFu : 0u;
                unsigned dnm = done[lastp]  ? 0xFFFFFFFFu : 0u;
                v = (g_P[cur][((p >> 1) - 1)*33 + w] & stm) | (g_E[(off[l] + p)*33 + w] & dnm);
            }
            g_P[nxt][p*33 + w] = v;
        }
        __syncthreads();
        cur = nxt;
    }

    for (int idx = tid; idx < 1024*32; idx += nth) {
        int t = idx >> 5, w = idx & 31;
        unsigned lo = g_P[cur][(t + 1)*33 + w];
        unsigned hi = g_P[cur][(t + 1)*33 + w + 1];
        g_AM[t*32 + w] = (lo >> 1) | (hi << 31);
    }
}

// ---------------- big GEMM: BM=128, BN=64, BK=16, 256 threads, 8x4 micro, FFMA2 ----------------
// ACT: 3=mask-score, 4=fused projection segments, 5=split-K partial (TRB=0)
// TRB: 1 -> B is [N,K] (B^T), 0 -> B is [K,N]
template<int ACT, int TRB>
__global__ __launch_bounds__(256) void gemm_big(
    const float* __restrict__ A, int lda,
    const float* __restrict__ B, int ldb,
    float* __restrict__ C, int ldc,
    int M, int K, SegPtrs seg)
{
    __shared__ __align__(16) float As[16][128];
    __shared__ __align__(16) float Bs[16][64];
    int tid = threadIdx.x;
    int m0 = blockIdx.y * 128;
    int n0;
    const float* Bp;
    float* Cp;
    const float* bp = nullptr;
    int sseg = 0;
    if (ACT == 4) {
        sseg = blockIdx.x >> 2;
        n0 = (blockIdx.x & 3) * 64;
        Bp = seg.W[sseg] + (size_t)n0 * ldb;
        Cp = seg.out[sseg];
        bp = (sseg == 3) ? seg.b : nullptr;
    } else {
        n0 = blockIdx.x * 64;
        Bp = TRB ? (B + (size_t)n0 * ldb) : (B + n0);
        Cp = C;
    }
    if (ACT == 5) {
        int z = blockIdx.z;
        A  += (size_t)z * K;            // column offset within lda
        Bp += (size_t)z * K * ldb;      // row offset (TRB=0)
        Cp += (size_t)z * M * ldc;
    }

    // global loaders
    int arow = tid >> 1, acg = (tid & 1) * 8;
    const float* Ald = A + (size_t)(m0 + arow) * lda + acg;
    int brow, bcg;
    if (TRB) { brow = tid >> 2; bcg = (tid & 3) * 4; }
    else     { brow = tid >> 4; bcg = (tid & 15) * 4; }
    const float* Bld = Bp + (size_t)brow * ldb + bcg;

    float4 pa0 = *(const float4*)(Ald);
    float4 pa1 = *(const float4*)(Ald + 4);
    float4 pb0 = *(const float4*)(Bld);

    int tx = tid & 15, ty = tid >> 4;
    U64 acc[4][4];
    #pragma unroll
    for (int r = 0; r < 4; r++)
        #pragma unroll
        for (int c = 0; c < 4; c++) acc[r][c].u = 0ull;

    for (int kc = 0; kc < K; kc += 16) {
        As[acg+0][arow]=pa0.x; As[acg+1][arow]=pa0.y; As[acg+2][arow]=pa0.z; As[acg+3][arow]=pa0.w;
        As[acg+4][arow]=pa1.x; As[acg+5][arow]=pa1.y; As[acg+6][arow]=pa1.z; As[acg+7][arow]=pa1.w;
        if (TRB) {
            Bs[bcg+0][brow]=pb0.x; Bs[bcg+1][brow]=pb0.y; Bs[bcg+2][brow]=pb0.z; Bs[bcg+3][brow]=pb0.w;
        } else {
            *(float4*)&Bs[brow][bcg] = pb0;
        }
        __syncthreads();
        if (kc + 16 < K) {
            pa0 = *(const float4*)(Ald + kc + 16);
            pa1 = *(const float4*)(Ald + kc + 16 + 4);
            pb0 = *(const float4*)(Bld + (TRB ? (size_t)(kc + 16) : (size_t)(kc + 16) * ldb));
        }
        #pragma unroll
        for (int kk = 0; kk < 16; kk++) {
            float4 a0 = *(const float4*)&As[kk][ty*8];
            float4 a1 = *(const float4*)&As[kk][ty*8 + 4];
            float4 b  = *(const float4*)&Bs[kk][tx*4];
            U64 ar[4], bb[4];
            ar[0].f = make_float2(a0.x, a0.y);
            ar[1].f = make_float2(a0.z, a0.w);
            ar[2].f = make_float2(a1.x, a1.y);
            ar[3].f = make_float2(a1.z, a1.w);
            bb[0].f = make_float2(b.x, b.x);
            bb[1].f = make_float2(b.y, b.y);
            bb[2].f = make_float2(b.z, b.z);
            bb[3].f = make_float2(b.w, b.w);
            #pragma unroll
            for (int r = 0; r < 4; r++)
                #pragma unroll
                for (int c = 0; c < 4; c++)
                    ffma2(acc[r][c], ar[r], bb[c]);
        }
        __syncthreads();
    }

    // epilogue
    int coln = n0 + tx*4;
    #pragma unroll
    for (int r2 = 0; r2 < 4; r2++) {
        #pragma unroll
        for (int h = 0; h < 2; h++) {
            int row = m0 + ty*8 + r2*2 + h;
            float v[4];
            #pragma unroll
            for (int c = 0; c < 4; c++) v[c] = h ? acc[r2][c].f.y : acc[r2][c].f.x;
            if (ACT == 3) {
                unsigned mw = g_AM[row*32 + (coln >> 5)];
                #pragma unroll
                for (int c = 0; c < 4; c++)
                    if (!((mw >> ((coln + c) & 31)) & 1u)) v[c] = 0.f;
            }
            if (ACT == 4) {
                if (bp) {
                    #pragma unroll
                    for (int c = 0; c < 4; c++) v[c] += bp[coln + c];
                }
                if (sseg < 2) {
                    #pragma unroll
                    for (int c = 0; c < 4; c++) v[c] = eluf(v[c]);
                }
            }
            float4 st = make_float4(v[0], v[1], v[2], v[3]);
            *(float4*)&Cp[(size_t)row * ldc + coln] = st;
        }
    }
}

// ---------------- small GEMM: BM=32, BN=64, BK=16, 128 threads, 4x4 micro, FFMA2 ----------------
// C[1024,256] = act(A[1024,256] @ B[256,256]^T + bias). ACT: 0=none, 2=mish
template<int ACT>
__global__ __launch_bounds__(128) void gemm_small(
    const float* __restrict__ A, const float* __restrict__ B,
    const float* __restrict__ bias, float* __restrict__ C)
{
    __shared__ __align__(16) float As[16][32];
    __shared__ __align__(16) float Bs[16][64];
    int tid = threadIdx.x;
    int m0 = blockIdx.y * 32;
    int n0 = blockIdx.x * 64;

    int arow = tid >> 2, acg = (tid & 3) * 4;
    int brow = tid >> 1, bcg = (tid & 1) * 8;
    const float* Ald = A + (size_t)(m0 + arow) * HH + acg;
    const float* Bld = B + (size_t)(n0 + brow) * HH + bcg;

    float4 pa = *(const float4*)(Ald);
    float4 pb0 = *(const float4*)(Bld);
    float4 pb1 = *(const float4*)(Bld + 4);

    int tx = tid & 15, ty = tid >> 4;
    U64 acc[2][4];
    #pragma unroll
    for (int r = 0; r < 2; r++)
        #pragma unroll
        for (int c = 0; c < 4; c++) acc[r][c].u = 0ull;

    for (int kc = 0; kc < HH; kc += 16) {
        As[acg+0][arow]=pa.x; As[acg+1][arow]=pa.y; As[acg+2][arow]=pa.z; As[acg+3][arow]=pa.w;
        Bs[bcg+0][brow]=pb0.x; Bs[bcg+1][brow]=pb0.y; Bs[bcg+2][brow]=pb0.z; Bs[bcg+3][brow]=pb0.w;
        Bs[bcg+4][brow]=pb1.x; Bs[bcg+5][brow]=pb1.y; Bs[bcg+6][brow]=pb1.z; Bs[bcg+7][brow]=pb1.w;
        __syncthreads();
        if (kc + 16 < HH) {
            pa  = *(const float4*)(Ald + kc + 16);
            pb0 = *(const float4*)(Bld + kc + 16);
            pb1 = *(const float4*)(Bld + kc + 16 + 4);
        }
        #pragma unroll
        for (int kk = 0; kk < 16; kk++) {
            float4 a = *(const float4*)&As[kk][ty*4];
            float4 b = *(const float4*)&Bs[kk][tx*4];
            U64 ar[2], bb[4];
            ar[0].f = make_float2(a.x, a.y);
            ar[1].f = make_float2(a.z, a.w);
            bb[0].f = make_float2(b.x, b.x);
            bb[1].f = make_float2(b.y, b.y);
            bb[2].f = make_float2(b.z, b.z);
            bb[3].f = make_float2(b.w, b.w);
            #pragma unroll
            for (int r = 0; r < 2; r++)
                #pragma unroll
                for (int c = 0; c < 4; c++)
                    ffma2(acc[r][c], ar[r], bb[c]);
        }
        __syncthreads();
    }

    int coln = n0 + tx*4;
    #pragma unroll
    for (int r2 = 0; r2 < 2; r2++) {
        #pragma unroll
        for (int h = 0; h < 2; h++) {
            int row = m0 + ty*4 + r2*2 + h;
            float v[4];
            #pragma unroll
            for (int c = 0; c < 4; c++) {
                v[c] = (h ? acc[r2][c].f.y : acc[r2][c].f.x) + bias[coln + c];
                if (ACT == 2) v[c] = mishf(v[c]);
            }
            *(float4*)&C[(size_t)row * HH + coln] = make_float4(v[0], v[1], v[2], v[3]);
        }
    }
}

// ---------------- row sums of K and Q ----------------
__global__ __launch_bounds__(256) void rowsums_kernel()
{
    __shared__ float sk[256], sq[256];
    int t = blockIdx.x, j = threadIdx.x;
    sk[j] = g_K[t*HH + j];
    sq[j] = g_Q[t*HH + j];
    __syncthreads();
    for (int s = 128; s > 0; s >>= 1) {
        if (j < s) { sk[j] += sk[j+s]; sq[j] += sq[j+s]; }
        __syncthreads();
    }
    if (j == 0) { g_sumk[t] = sk[0]; g_sumq[t] = sq[0]; }
}

// ---------------- denom[t] = max(sumq[t] * sum_u mask[t][u]*sumk[u], 1e-5) ----------------
__global__ __launch_bounds__(256) void denom_kernel()
{
    __shared__ float red[256];
    int t = blockIdx.x, j = threadIdx.x;
    float s = 0.f;
    for (int u = j; u < TT; u += 256) {
        unsigned mw = g_AM[t*32 + (u >> 5)];
        if ((mw >> (u & 31)) & 1u) s += g_sumk[u];
    }
    red[j] = s;
    __syncthreads();
    for (int st = 128; st > 0; st >>= 1) {
        if (j < st) red[j] += red[j+st];
        __syncthreads();
    }
    if (j == 0) g_denom[t] = fmaxf(red[0] * g_sumq[t], 1e-5f);
}

// ---------------- combine split-K partials and divide by denom ----------------
__global__ __launch_bounds__(256) void combine_div()
{
    int i = blockIdx.x * 256 + threadIdx.x;    // 65536 float4s total
    const float4* p = (const float4*)g_SVP;
    float4 a = p[i], b = p[i + 65536], c = p[i + 131072], d = p[i + 196608];
    int row = i >> 6;
    float inv = 1.0f / g_denom[row];
    float4 o;
    o.x = (a.x + b.x + c.x + d.x) * inv;
    o.y = (a.y + b.y + c.y + d.y) * inv;
    o.z = (a.z + b.z + c.z + d.z) * inv;
    o.w = (a.w + b.w + c.w + d.w) * inv;
    ((float4*)g_OUT)[i] = o;
}

// ---------------- final: layernorm(H3 + SKIP) ----------------
__global__ __launch_bounds__(256) void ln_kernel(const float* __restrict__ lnw,
                                                 const float* __restrict__ lnb,
                                                 float* __restrict__ out)
{
    __shared__ float red[256];
    int t = blockIdx.x, j = threadIdx.x;
    float h = g_H3[t*HH + j] + g_SKIP[t*HH + j];
    red[j] = h;
    __syncthreads();
    for (int s = 128; s > 0; s >>= 1) { if (j < s) red[j] += red[j+s]; __syncthreads(); }
    float mu = red[0] * (1.0f / HH);
    __syncthreads();
    float d = h - mu;
    red[j] = d * d;
    __syncthreads();
    for (int s = 128; s > 0; s >>= 1) { if (j < s) red[j] += red[j+s]; __syncthreads(); }
    float var = red[0] * (1.0f / HH);
    out[t*HH + j] = d * rsqrtf(var + 1e-5f) * lnw[j] + lnb[j];
}

// ---------------- launch ----------------
extern "C" void kernel_launch(void* const* d_in, const int* in_sizes, int n_in,
                              void* d_out, int out_size)
{
    const float* x     = (const float*)d_in[0];
    const int*   start = (const int*)  d_in[3];
    const int*   done  = (const int*)  d_in[4];
    const float* Wk    = (const float*)d_in[5];
    const float* Wq    = (const float*)d_in[6];
    const float* Wv    = (const float*)d_in[7];
    const float* Wskip = (const float*)d_in[8];
    const float* bskip = (const float*)d_in[9];
    const float* W1    = (const float*)d_in[10];
    const float* b1    = (const float*)d_in[11];
    const float* W2    = (const float*)d_in[12];
    const float* b2    = (const float*)d_in[13];
    const float* W3    = (const float*)d_in[14];
    const float* b3    = (const float*)d_in[15];
    const float* lnw   = (const float*)d_in[16];
    const float* lnb   = (const float*)d_in[17];
    float* out = (float*)d_out;

    float *pK, *pQ, *pV, *pSKIP, *pS, *pSVP, *pOUT, *pH1, *pH2, *pH3;
    cudaGetSymbolAddress((void**)&pK,    g_K);
    cudaGetSymbolAddress((void**)&pQ,    g_Q);
    cudaGetSymbolAddress((void**)&pV,    g_V);
    cudaGetSymbolAddress((void**)&pSKIP, g_SKIP);
    cudaGetSymbolAddress((void**)&pS,    g_S);
    cudaGetSymbolAddress((void**)&pSVP,  g_SVP);
    cudaGetSymbolAddress((void**)&pOUT,  g_OUT);
    cudaGetSymbolAddress((void**)&pH1,   g_H1);
    cudaGetSymbolAddress((void**)&pH2,   g_H2);
    cudaGetSymbolAddress((void**)&pH3,   g_H3);

    SegPtrs sp;
    sp.W[0] = Wk; sp.W[1] = Wq; sp.W[2] = Wv; sp.W[3] = Wskip;
    sp.out[0] = pK; sp.out[1] = pQ; sp.out[2] = pV; sp.out[3] = pSKIP;
    sp.b = bskip;
    SegPtrs sp0 = {};

    mask_kernel<<<1, 1024>>>(start, done);
    // fused QKV+skip projection: one 1024x1024x256 GEMM wave (128 CTAs)
    gemm_big<4,1><<<dim3(16,8), 256>>>(x, DD, nullptr, DD, nullptr, HH, TT, DD, sp);
    rowsums_kernel<<<TT, 256>>>();
    // masked scores S = Q K^T (1024x1024x256, 128 CTAs)
    gemm_big<3,1><<<dim3(16,8), 256>>>(pQ, HH, pK, HH, pS, TT, TT, HH, sp0);
    denom_kernel<<<TT, 256>>>();
    // numer = S V, split-K 4-way (128 CTAs), then combine + divide
    gemm_big<5,0><<<dim3(4,8,4), 256>>>(pS, TT, pV, HH, pSVP, HH, TT, 256, sp0);
    combine_div<<<256, 256>>>();
    // MLP
    gemm_small<2><<<dim3(4,32), 128>>>(pOUT, W1, b1, pH1);
    gemm_small<2><<<dim3(4,32), 128>>>(pH1,  W2, b2, pH2);
    gemm_small<0><<<dim3(4,32), 128>>>(pH2,  W3, b3, pH3);
    ln_kernel<<<TT, 256>>>(lnw, lnb, out);
}